// round 8
// baseline (speedup 1.0000x reference)
#include <cuda_runtime.h>
#include <cstdint>

#define WW 128
#define HH 128
#define NP 2048
#define DIMU 768
#define PTOT (HH*WW)

// ---- scratch (device globals: no allocation allowed) ----
__device__ __align__(16) float g_imr[PTOT];
__device__ __align__(16) float g_img[PTOT];
__device__ __align__(16) float g_imb[PTOT];

// ---- packed f32x2 helpers (sm_103a FFMA2) ----
__device__ __forceinline__ unsigned long long pk2(float lo, float hi) {
    unsigned long long v;
    asm("mov.b64 %0, {%1, %2};" : "=l"(v) : "f"(lo), "f"(hi));
    return v;
}
__device__ __forceinline__ unsigned long long ffma2(unsigned long long a,
                                                    unsigned long long b,
                                                    unsigned long long c) {
    unsigned long long d;
    asm("fma.rn.f32x2 %0, %1, %2, %3;" : "=l"(d) : "l"(a), "l"(b), "l"(c));
    return d;
}
__device__ __forceinline__ uint32_t smem_u32(const void* p) {
    uint32_t a;
    asm("{ .reg .u64 t; cvta.to.shared.u64 t, %1; cvt.u32.u64 %0, t; }"
        : "=r"(a) : "l"(p));
    return a;
}

// ============================================================
// K1: fused preprocess + tiled rasterizer (R7 config, best).
// 128 blocks (8x16 grid of 16x8-px tiles), 256 threads.
// ============================================================
__global__ __launch_bounds__(256, 1) void k_praster(
    const float* __restrict__ xyz, const float* __restrict__ scaling,
    const float* __restrict__ rotation, const float* __restrict__ features,
    const float* __restrict__ opacity)
{
    __shared__ __align__(16) float4 sA[2][256];   // gx, gy, 0.5A, B
    __shared__ __align__(16) float4 sB[2][256];   // 0.5C, op, cr, cg
    __shared__ __align__(16) float  scb[2][256];  // cb
    __shared__ int swc[2][8];

    const int tid  = threadIdx.x;
    const int lane = tid & 31;
    const int wid  = tid >> 5;

    const int x0 = (blockIdx.x & 7) << 4;
    const int y0 = (blockIdx.x >> 3) << 3;
    const int tx = tid & 15, ty = (tid >> 4) & 7;     // pixel for tid<128
    const float px = (float)(x0 + tx) + 0.5f;
    const float py = (float)(y0 + ty) + 0.5f;
    const float txmin = (float)x0 + 0.5f, txmax = (float)x0 + 15.5f;
    const float tymin = (float)y0 + 0.5f, tymax = (float)y0 + 7.5f;
    const bool rasterer = (tid < 128);

    float accr = 0.0f, accg = 0.0f, accb = 0.0f;

    // ---- prefetch chunk 0 ----
    float2 nxy = ((const float2*)xyz)[tid];
    float2 nsc = ((const float2*)scaling)[tid];
    float  nrt = rotation[tid];
    float  nop = opacity[tid];
    float  nf0 = features[3*tid + 0];
    float  nf1 = features[3*tid + 1];
    float  nf2 = features[3*tid + 2];

    #pragma unroll 1
    for (int ck = 0; ck < NP / 256; ck++) {
        const int c = ck & 1;
        float2 xy = nxy; float2 sc = nsc;
        float rt = nrt, op = nop, f0 = nf0, f1 = nf1, f2 = nf2;
        if (ck + 1 < NP / 256) {
            const int ngi = (ck + 1) * 256 + tid;
            nxy = ((const float2*)xyz)[ngi];
            nsc = ((const float2*)scaling)[ngi];
            nrt = rotation[ngi];
            nop = opacity[ngi];
            nf0 = features[3*ngi + 0];
            nf1 = features[3*ngi + 1];
            nf2 = features[3*ngi + 2];
        }

        // ---- preprocess (fast intrinsics) ----
        float e0 = __expf(2.0f * xy.x);
        float e1 = __expf(2.0f * xy.y);
        float gx = __fdividef(128.0f * e0, e0 + 1.0f);   // 0.5*(tanh+1)*W
        float gy = __fdividef(128.0f * e1, e1 + 1.0f);
        float s0 = fabsf(sc.x + 0.5f);
        float s1 = fabsf(sc.y + 0.5f);
        float th = 6.283185307179586f *
                   __fdividef(1.0f, 1.0f + __expf(-rt));
        float sn, cs; __sincosf(th, &sn, &cs);
        float a = cs * s0, b = -sn * s1, dd = sn * s0, ee = cs * s1;
        float cxx = a*a + b*b;
        float cxy = a*dd + b*ee;
        float cyy = dd*dd + ee*ee;
        float det = cxx*cyy - cxy*cxy;
        float inv = __fdividef(1.0f, det);
        float hA =  0.5f * cyy * inv;
        float Bc = -cxy * inv;
        float hC =  0.5f * cxx * inv;
        float smax = __logf(255.0f * op);   // alpha>=1/255 <=> sigma<=smax

        bool keep = false;
        if (det > 0.0f && smax > 0.0f) {
            float rx = sqrtf(2.0f * smax * cxx) * 1.001f + 0.02f;
            float ry = sqrtf(2.0f * smax * cyy) * 1.001f + 0.02f;
            keep = (gx + rx >= txmin) && (gx - rx <= txmax) &&
                   (gy + ry >= tymin) && (gy - ry <= tymax);
        }

        // ---- deterministic ballot compaction (double-buffered) ----
        unsigned mask = __ballot_sync(0xffffffffu, keep);
        if (lane == 0) swc[c][wid] = __popc(mask);
        __syncthreads();
        int bp = 0, total = 0;
        #pragma unroll
        for (int w = 0; w < 8; w++) {
            int cw = swc[c][w];
            bp += (w < wid) ? cw : 0;
            total += cw;
        }
        if (keep) {
            int pos = bp + __popc(mask & ((1u << lane) - 1u));
            sA[c][pos]  = make_float4(gx, gy, hA, Bc);
            sB[c][pos]  = make_float4(hC, op, f0, f1);
            scb[c][pos] = f2;
        }
        __syncthreads();

        // ---- raster accumulate (pixel-owning threads only) ----
        if (rasterer) {
            #pragma unroll 2
            for (int j = 0; j < total; j++) {
                float4 a4 = sA[c][j];
                float4 b4 = sB[c][j];
                float  cb = scb[c][j];
                float dx = a4.x - px;
                float dy = a4.y - py;
                float sig = a4.z * dx * dx + a4.w * dx * dy + b4.x * dy * dy;
                float al = fminf(0.999f, b4.y * __expf(-sig));
                al = (sig >= 0.0f && al >= (1.0f / 255.0f)) ? al : 0.0f;
                accr = fmaf(al, b4.z, accr);
                accg = fmaf(al, b4.w, accg);
                accb = fmaf(al, cb,   accb);
            }
        }
    }

    if (rasterer) {
        const int p = (y0 + ty) * WW + (x0 + tx);
        g_imr[p] = fminf(1.0f, fmaxf(0.0f, accr));
        g_img[p] = fminf(1.0f, fmaxf(0.0f, accg));
        g_imb[p] = fminf(1.0f, fmaxf(0.0f, accb));
    }
}

// ============================================================
// K2: up-projection with TMA bulk stores.
// Block = (1024 px) x (24 dims); grid (16,32)=512 blocks
// (single wave). 6 stages of 4 dims: compute -> smem stage
// (double-buffered 16KB) -> cp.async.bulk smem->gmem. The TMA
// engine does all global stores; SM issues ~24 instrs of store
// work per block instead of 16K lane-STGs.
// ============================================================
#define D_BLK 24
#define NSTAGE (D_BLK / 4)
__global__ __launch_bounds__(256) void k_up(const float* __restrict__ w_up,
                                            const float* __restrict__ b_up,
                                            float* __restrict__ out) {
    // packed duplicated weights: [d][0]={wr2,wg2}, [d][1]={wb2,bias2}
    __shared__ __align__(16) ulonglong2 sw2[D_BLK][2];
    __shared__ __align__(16) float sbuf[2][4][1024];   // 32 KB staging

    const int tid = threadIdx.x;                   // 256
    const int db  = blockIdx.y * D_BLK;
    const int bx  = blockIdx.x;
    if (tid < D_BLK) {
        int d = db + tid;
        float wr = w_up[3*d + 0], wg = w_up[3*d + 1], wb = w_up[3*d + 2];
        float bi = b_up[d];
        ulonglong2 a; a.x = pk2(wr, wr); a.y = pk2(wg, wg);
        ulonglong2 b; b.x = pk2(wb, wb); b.y = pk2(bi, bi);
        sw2[tid][0] = a;
        sw2[tid][1] = b;
    }

    const int p4 = bx * 256 + tid;                 // float4 pixel index
    float4 R = ((const float4*)g_imr)[p4];
    float4 G = ((const float4*)g_img)[p4];
    float4 B = ((const float4*)g_imb)[p4];
    unsigned long long r01 = pk2(R.x, R.y), r23 = pk2(R.z, R.w);
    unsigned long long g01 = pk2(G.x, G.y), g23 = pk2(G.z, G.w);
    unsigned long long b01 = pk2(B.x, B.y), b23 = pk2(B.z, B.w);
    __syncthreads();

    const uint32_t sb0 = smem_u32(&sbuf[0][0][0]);

    #pragma unroll 1
    for (int s = 0; s < NSTAGE; s++) {
        const int c = s & 1;

        // recycle buffer c: copies committed at stage s-2 must be read out
        if (s >= 2) {
            if (tid == 0)
                asm volatile("cp.async.bulk.wait_group.read 1;" ::: "memory");
            __syncthreads();
        }

        // compute 4 dims for this thread's 4 pixels -> smem stage
        #pragma unroll
        for (int k = 0; k < 4; k++) {
            const int d = s * 4 + k;
            ulonglong2 wa = sw2[d][0];     // {wr2, wg2}
            ulonglong2 wb = sw2[d][1];     // {wb2, bias2}
            unsigned long long vx =
                ffma2(b01, wb.x, ffma2(g01, wa.y, ffma2(r01, wa.x, wb.y)));
            unsigned long long vy =
                ffma2(b23, wb.x, ffma2(g23, wa.y, ffma2(r23, wa.x, wb.y)));
            float4 v;
            asm("mov.b64 {%0, %1}, %2;" : "=f"(v.x), "=f"(v.y) : "l"(vx));
            asm("mov.b64 {%0, %1}, %2;" : "=f"(v.z), "=f"(v.w) : "l"(vy));
            *(float4*)&sbuf[c][k][tid * 4] = v;
        }
        __syncthreads();

        // one thread pushes 4 x 4KB bulk copies to the TMA engine
        if (tid == 0) {
            asm volatile("fence.proxy.async.shared::cta;" ::: "memory");
            #pragma unroll
            for (int k = 0; k < 4; k++) {
                const float* gp = out + (size_t)(db + s * 4 + k) * PTOT
                                      + (size_t)bx * 1024;
                uint32_t sa = sb0 + (uint32_t)(c * 4 + k) * 4096u;
                asm volatile(
                    "cp.async.bulk.global.shared::cta.bulk_group [%0], [%1], 4096;"
                    :: "l"(gp), "r"(sa) : "memory");
            }
            asm volatile("cp.async.bulk.commit_group;" ::: "memory");
        }
    }

    // drain before smem is torn down at exit
    if (tid == 0)
        asm volatile("cp.async.bulk.wait_group.read 0;" ::: "memory");
}

// ============================================================
extern "C" void kernel_launch(void* const* d_in, const int* in_sizes, int n_in,
                              void* d_out, int out_size) {
    // metadata order: x, xyz, scaling, rotation, features, opacity, w_up, b_up
    const float* xyz      = (const float*)d_in[1];
    const float* scaling  = (const float*)d_in[2];
    const float* rotation = (const float*)d_in[3];
    const float* features = (const float*)d_in[4];
    const float* opacity  = (const float*)d_in[5];
    const float* w_up     = (const float*)d_in[6];
    const float* b_up     = (const float*)d_in[7];
    float* out = (float*)d_out;

    k_praster<<<128, 256>>>(xyz, scaling, rotation, features, opacity);
    k_up<<<dim3(PTOT / 1024, DIMU / D_BLK), 256>>>(w_up, b_up, out);
}